// round 11
// baseline (speedup 1.0000x reference)
#include <cuda_runtime.h>
#include <cuda_fp16.h>
#include <stdint.h>

// Problem constants (fixed by the dataset)
#define BB   16
#define NN   2048
#define CC   256
#define KK   16
#define KP1  17
#define OUTC 259   // 3 + C

// Scratch for knn indices (device global: allocation-free)
__device__ int g_knn[BB * NN * KK];

// order-preserving fp32 -> u32 map
__device__ __forceinline__ unsigned f2u(float f) {
    unsigned u = __float_as_uint(f);
    return u ^ (((unsigned)((int)u >> 31)) | 0x80000000u);
}

#define FULL 0xffffffffu

// ---------------------------------------------------------------------------
// Kernel A: warp-per-query exact top-17, SORTED-ACROSS-LANES list.
// Lanes 0..16 hold (ku, kidx) sorted ascending by ku, stable (equal keys in
// ascending idx, since candidates are processed in ascending m). Insert of an
// accepted candidate: rank p = popc(ballot(ku <= cu)); lane p takes the
// candidate, lanes > p shift up by one, lane 16 is evicted (= largest key,
// largest idx among ties -> exact top_k semantics). Strict accept (cu < maxu)
// keeps incumbents on boundary ties. Lane 0 ends as the reference's sorted
// column 0 (self): min key, min idx -> simply dropped; lanes 1..16 emit.
// ---------------------------------------------------------------------------
#define QW 8   // query warps per block (256 threads)
__global__ __launch_bounds__(256)
void knn_kernel(const float* __restrict__ xyz, float* __restrict__ out)
{
    __shared__ float4 sp[NN];   // 32 KB: x, y, z, |p|^2

    const int b    = blockIdx.y;
    const int tid  = threadIdx.x;
    const int lane = tid & 31;
    const int warp = tid >> 5;
    const float* xb = xyz + (size_t)b * NN * 3;

    for (int m = tid; m < NN; m += 256) {
        float x = xb[m * 3 + 0];
        float y = xb[m * 3 + 1];
        float z = xb[m * 3 + 2];
        sp[m] = make_float4(x, y, z, x * x + y * y + z * z);
    }
    __syncthreads();

    const int n = blockIdx.x * QW + warp;     // this warp's query
    const float4 q = sp[n];

    const bool holder = (lane < KP1);
    // holders: distinct ascending sentinels (real keys are far below 0xFFFFFF00)
    // non-holders: 0xFFFFFFFF so they never set ballot bits (ku <= cu is false)
    unsigned ku   = holder ? (0xFFFFFF00u | (unsigned)lane) : 0xFFFFFFFFu;
    unsigned kidx = 0u;
    unsigned maxu = 0xFFFFFF00u | (KP1 - 1);  // current 17th = lane 16's key

    for (int step = 0; step < NN / 64; step++) {
        const int m0 = step * 64 + lane;
        float4 p0 = sp[m0];
        float4 p1 = sp[m0 + 32];
        float dot0 = q.x * p0.x + q.y * p0.y + q.z * p0.z;
        float dot1 = q.x * p1.x + q.y * p1.y + q.z * p1.z;
        float d20  = q.w + p0.w - 2.0f * dot0;   // same formula as reference
        float d21  = q.w + p1.w - 2.0f * dot1;
        unsigned u0 = f2u(d20);
        unsigned u1 = f2u(d21);

        unsigned bal0 = __ballot_sync(FULL, u0 < maxu);
        unsigned bal1 = __ballot_sync(FULL, u1 < maxu);

        while (bal0) {                        // ascending m within group 0
            const int src = __ffs(bal0) - 1;
            bal0 &= bal0 - 1;
            unsigned cu = __shfl_sync(FULL, u0, src);
            if (cu < maxu) {                  // strict: boundary tie -> reject
                unsigned cm = (unsigned)(step * 64 + src);
                unsigned rb = __ballot_sync(FULL, ku <= cu);
                int p = __popc(rb);           // insert rank (<= 16)
                unsigned kuu = __shfl_up_sync(FULL, ku, 1);
                unsigned kiu = __shfl_up_sync(FULL, kidx, 1);
                if (holder) {
                    if (lane == p)      { ku = cu;  kidx = cm;  }
                    else if (lane > p)  { ku = kuu; kidx = kiu; }
                }
                maxu = __shfl_sync(FULL, ku, KP1 - 1);
            }
        }
        while (bal1) {                        // then group 1 (m0+32)
            const int src = __ffs(bal1) - 1;
            bal1 &= bal1 - 1;
            unsigned cu = __shfl_sync(FULL, u1, src);
            if (cu < maxu) {
                unsigned cm = (unsigned)(step * 64 + 32 + src);
                unsigned rb = __ballot_sync(FULL, ku <= cu);
                int p = __popc(rb);
                unsigned kuu = __shfl_up_sync(FULL, ku, 1);
                unsigned kiu = __shfl_up_sync(FULL, kidx, 1);
                if (holder) {
                    if (lane == p)      { ku = cu;  kidx = cm;  }
                    else if (lane > p)  { ku = kuu; kidx = kiu; }
                }
                maxu = __shfl_sync(FULL, ku, KP1 - 1);
            }
        }
    }

    // lane 0 == self (sorted column 0); lanes 1..16 are the k neighbors
    const bool keep = (lane >= 1) && (lane < KP1);

    float4 pN = make_float4(0.f, 0.f, 0.f, 0.f);
    if (keep) pN = sp[kidx];
    float sx = pN.x, sy = pN.y, sz = pN.z;
#pragma unroll
    for (int o = 16; o > 0; o >>= 1) {
        sx += __shfl_xor_sync(FULL, sx, o);
        sy += __shfl_xor_sync(FULL, sy, o);
        sz += __shfl_xor_sync(FULL, sz, o);
    }
    if (lane == 0) {
        const float inv = 1.0f / (float)KK;
        size_t ob = ((size_t)b * NN + n) * OUTC;
        out[ob + 0] = sx * inv - q.x;
        out[ob + 1] = sy * inv - q.y;
        out[ob + 2] = sz * inv - q.z;
    }

    if (keep) g_knn[((size_t)b * NN + n) * KK + (lane - 1)] = (int)kidx;
}

// ---------------------------------------------------------------------------
// Kernel B: feature gather + mean - self, fp16x2 channel pairing.
// Block covers 16 channels via 8 half2 rows (65.5 KB smem) -> 2 blocks/SM,
// 2048 threads/SM (~100% occupancy). Row c holds half2(ch c0+c, ch c0+c+8),
// pitch 2049 -> the 8 channel lanes of a group hit banks (c + idx) % 32,
// conflict-free within the group.
// ---------------------------------------------------------------------------
#define CTP    16           // channels per block (8 half2 rows)
#define CROWS  8
#define PITCH  2049
#define SMEMB  (CROWS * PITCH * (int)sizeof(__half2))

__global__ __launch_bounds__(1024)
void gather_kernel(const float* __restrict__ features, float* __restrict__ out)
{
    extern __shared__ __half2 fsm[];   // [8][PITCH]

    const int b   = blockIdx.y;
    const int c0  = blockIdx.x * CTP;
    const int tid = threadIdx.x;

    // Stage: pack channels (c0+c, c0+c+8) as half2 rows
    const float* fbase = features + ((size_t)b * CC + c0) * NN;
    for (int i = tid; i < CROWS * NN; i += 1024) {
        int c = i >> 11;          // 0..7
        int m = i & (NN - 1);
        float v0 = fbase[(size_t)c * NN + m];
        float v1 = fbase[(size_t)(c + CROWS) * NN + m];
        fsm[c * PITCH + m] = __floats2half2_rn(v0, v1);
    }
    __syncthreads();

    const int c  = tid & 7;       // half2 row
    const int n0 = tid >> 3;      // 0..127

    const int*     knn_b = g_knn + (size_t)b * NN * KK;
    const __half2* frow  = fsm + c * PITCH;
    float* outc = out + (size_t)b * NN * OUTC + 3 + c0 + c;

#pragma unroll 2
    for (int n = n0; n < NN; n += 128) {
        const int4* kr = (const int4*)(knn_b + n * KK);
        int4 k0 = __ldg(kr + 0);
        int4 k1 = __ldg(kr + 1);
        int4 k2 = __ldg(kr + 2);
        int4 k3 = __ldg(kr + 3);

        float2 a0 = __half22float2(frow[k0.x]);
        float2 a1 = __half22float2(frow[k0.y]);
        float2 a2 = __half22float2(frow[k0.z]);
        float2 a3 = __half22float2(frow[k0.w]);
        float2 a4 = __half22float2(frow[k1.x]);
        float2 a5 = __half22float2(frow[k1.y]);
        float2 a6 = __half22float2(frow[k1.z]);
        float2 a7 = __half22float2(frow[k1.w]);
        float s0 = a0.x + a1.x + a2.x + a3.x + a4.x + a5.x + a6.x + a7.x;
        float s1 = a0.y + a1.y + a2.y + a3.y + a4.y + a5.y + a6.y + a7.y;
        a0 = __half22float2(frow[k2.x]);
        a1 = __half22float2(frow[k2.y]);
        a2 = __half22float2(frow[k2.z]);
        a3 = __half22float2(frow[k2.w]);
        a4 = __half22float2(frow[k3.x]);
        a5 = __half22float2(frow[k3.y]);
        a6 = __half22float2(frow[k3.z]);
        a7 = __half22float2(frow[k3.w]);
        s0 += a0.x + a1.x + a2.x + a3.x + a4.x + a5.x + a6.x + a7.x;
        s1 += a0.y + a1.y + a2.y + a3.y + a4.y + a5.y + a6.y + a7.y;

        float2 self = __half22float2(frow[n]);
        float* o = outc + (size_t)n * OUTC;
        o[0]     = s0 * (1.0f / (float)KK) - self.x;
        o[CROWS] = s1 * (1.0f / (float)KK) - self.y;
    }
}

// ---------------------------------------------------------------------------
extern "C" void kernel_launch(void* const* d_in, const int* in_sizes, int n_in,
                              void* d_out, int out_size)
{
    const float* xyz      = (const float*)d_in[0];
    const float* features = (const float*)d_in[1];
    float* out = (float*)d_out;

    knn_kernel<<<dim3(NN / QW, BB), 256>>>(xyz, out);

    cudaFuncSetAttribute(gather_kernel,
                         cudaFuncAttributeMaxDynamicSharedMemorySize, SMEMB);
    gather_kernel<<<dim3(CC / CTP, BB), 1024, SMEMB>>>(features, out);
}

// round 12
// speedup vs baseline: 1.0692x; 1.0692x over previous
#include <cuda_runtime.h>
#include <cuda_fp16.h>
#include <stdint.h>

// Problem constants (fixed by the dataset)
#define BB   16
#define NN   2048
#define CC   256
#define KK   16
#define KP1  17
#define OUTC 259   // 3 + C

// Scratch for knn indices (device global: allocation-free)
__device__ int g_knn[BB * NN * KK];

// order-preserving fp32 -> u32 map
__device__ __forceinline__ unsigned f2u(float f) {
    unsigned u = __float_as_uint(f);
    return u ^ (((unsigned)((int)u >> 31)) | 0x80000000u);
}

#define FULL 0xffffffffu

// ---------------------------------------------------------------------------
// Kernel A: warp-per-query exact top-17 (R10 REDUX insert, x2-unrolled scan).
// 17 best (key = u32 sortable d2, payload = idx) live one-per-lane on lanes
// 0..16. Each iteration scans 64 candidates (2/lane); ballots processed
// serially in ascending m (group 0 then group 1), warp-uniform. Eviction:
// among holders with key == max, evict largest idx (top_k tie semantics);
// strict accept keeps incumbents on boundary ties. (key, idx) pairs unique
// -> single eviction always.
// ---------------------------------------------------------------------------
#define QW 8   // query warps per block (256 threads)
__global__ __launch_bounds__(256)
void knn_kernel(const float* __restrict__ xyz, float* __restrict__ out)
{
    __shared__ float4 sp[NN];   // 32 KB: x, y, z, |p|^2

    const int b    = blockIdx.y;
    const int tid  = threadIdx.x;
    const int lane = tid & 31;
    const int warp = tid >> 5;
    const float* xb = xyz + (size_t)b * NN * 3;

    for (int m = tid; m < NN; m += 256) {
        float x = xb[m * 3 + 0];
        float y = xb[m * 3 + 1];
        float z = xb[m * 3 + 2];
        sp[m] = make_float4(x, y, z, x * x + y * y + z * z);
    }
    __syncthreads();

    const int n = blockIdx.x * QW + warp;     // this warp's query
    const float4 q = sp[n];

    const bool holder = (lane < KP1);
    // distinct huge sentinels (real u keys are far below 0xFFFFFF00)
    unsigned ku   = holder ? (0xFFFFFF00u | (unsigned)lane) : 0u;
    unsigned kidx = 0u;
    unsigned maxu = 0xFFFFFF00u | (KP1 - 1);  // current 17th (max of holders)

    for (int step = 0; step < NN / 64; step++) {
        const int m0 = step * 64 + lane;
        float4 p0 = sp[m0];                   // 2 independent LDS.128 chains
        float4 p1 = sp[m0 + 32];
        float dot0 = q.x * p0.x + q.y * p0.y + q.z * p0.z;
        float dot1 = q.x * p1.x + q.y * p1.y + q.z * p1.z;
        float d20  = q.w + p0.w - 2.0f * dot0;   // same formula as reference
        float d21  = q.w + p1.w - 2.0f * dot1;
        unsigned u0 = f2u(d20);
        unsigned u1 = f2u(d21);

        unsigned bal0 = __ballot_sync(FULL, u0 < maxu);
        unsigned bal1 = __ballot_sync(FULL, u1 < maxu);

        while (bal0) {                        // ascending m within group 0
            const int src = __ffs(bal0) - 1;
            bal0 &= bal0 - 1;
            unsigned cu = __shfl_sync(FULL, u0, src);
            unsigned cm = (unsigned)(step * 64 + src);
            if (cu < maxu) {                  // strict: boundary tie -> reject
                bool ismax = holder && (ku == maxu);
                unsigned emx = __reduce_max_sync(FULL, ismax ? kidx : 0u);
                if (ismax && kidx == emx) { ku = cu; kidx = cm; }
                maxu = __reduce_max_sync(FULL, holder ? ku : 0u);
            }
        }
        while (bal1) {                        // then group 1 (m0+32)
            const int src = __ffs(bal1) - 1;
            bal1 &= bal1 - 1;
            unsigned cu = __shfl_sync(FULL, u1, src);
            unsigned cm = (unsigned)(step * 64 + 32 + src);
            if (cu < maxu) {
                bool ismax = holder && (ku == maxu);
                unsigned emx = __reduce_max_sync(FULL, ismax ? kidx : 0u);
                if (ismax && kidx == emx) { ku = cu; kidx = cm; }
                maxu = __reduce_max_sync(FULL, holder ? ku : 0u);
            }
        }
    }

    // identify self = min key, lowest idx among exact ties (sorted column 0)
    unsigned minu = __reduce_min_sync(FULL, holder ? ku : 0xFFFFFFFFu);
    bool ismin = holder && (ku == minu);
    unsigned mni = __reduce_min_sync(FULL, ismin ? kidx : 0xFFFFFFFFu);
    bool keep = holder && !(ismin && kidx == mni);

    // mean of neighbor xyz (16 keepers)
    float4 pN = make_float4(0.f, 0.f, 0.f, 0.f);
    if (keep) pN = sp[kidx];
    float sx = pN.x, sy = pN.y, sz = pN.z;
#pragma unroll
    for (int o = 16; o > 0; o >>= 1) {
        sx += __shfl_xor_sync(FULL, sx, o);
        sy += __shfl_xor_sync(FULL, sy, o);
        sz += __shfl_xor_sync(FULL, sz, o);
    }
    if (lane == 0) {
        const float inv = 1.0f / (float)KK;
        size_t ob = ((size_t)b * NN + n) * OUTC;
        out[ob + 0] = sx * inv - q.x;
        out[ob + 1] = sy * inv - q.y;
        out[ob + 2] = sz * inv - q.z;
    }

    // emit knn indices (order within row irrelevant: gather sums them)
    unsigned kb = __ballot_sync(FULL, keep);
    int pos = __popc(kb & ((1u << lane) - 1u));
    if (keep) g_knn[((size_t)b * NN + n) * KK + pos] = (int)kidx;
}

// ---------------------------------------------------------------------------
// Kernel B: feature gather + mean - self, fp16x2 channel pairing (R10 exact).
// Block covers 32 channels: SMEM row c (0..15) holds half2(ch c0+c, ch c0+c+16)
// for all 2048 points, pitch 2049 -> the 16 channel lanes of a group hit banks
// (c + idx) % 32, conflict-free. One LDS gather feeds TWO output channels.
// ---------------------------------------------------------------------------
#define CTP    32           // channels per block (16 half2 rows)
#define PITCH  2049
#define SMEMB  (16 * PITCH * (int)sizeof(__half2))

__global__ __launch_bounds__(1024)
void gather_kernel(const float* __restrict__ features, float* __restrict__ out)
{
    extern __shared__ __half2 fsm[];   // [16][PITCH]

    const int b   = blockIdx.y;
    const int c0  = blockIdx.x * CTP;
    const int tid = threadIdx.x;

    // Stage: pack channels (c0+c, c0+c+16) as half2 rows
    const float* fbase = features + ((size_t)b * CC + c0) * NN;
    for (int i = tid; i < 16 * NN; i += 1024) {
        int c = i >> 11;          // 0..15
        int m = i & (NN - 1);
        float v0 = fbase[(size_t)c * NN + m];
        float v1 = fbase[(size_t)(c + 16) * NN + m];
        fsm[c * PITCH + m] = __floats2half2_rn(v0, v1);
    }
    __syncthreads();

    const int c  = tid & 15;      // half2 row
    const int n0 = tid >> 4;      // 0..63

    const int*     knn_b = g_knn + (size_t)b * NN * KK;
    const __half2* frow  = fsm + c * PITCH;
    float* outc = out + (size_t)b * NN * OUTC + 3 + c0 + c;

#pragma unroll 2
    for (int n = n0; n < NN; n += 64) {
        const int4* kr = (const int4*)(knn_b + n * KK);
        int4 k0 = __ldg(kr + 0);
        int4 k1 = __ldg(kr + 1);
        int4 k2 = __ldg(kr + 2);
        int4 k3 = __ldg(kr + 3);

        float2 a0 = __half22float2(frow[k0.x]);
        float2 a1 = __half22float2(frow[k0.y]);
        float2 a2 = __half22float2(frow[k0.z]);
        float2 a3 = __half22float2(frow[k0.w]);
        float2 a4 = __half22float2(frow[k1.x]);
        float2 a5 = __half22float2(frow[k1.y]);
        float2 a6 = __half22float2(frow[k1.z]);
        float2 a7 = __half22float2(frow[k1.w]);
        float s0 = a0.x + a1.x + a2.x + a3.x + a4.x + a5.x + a6.x + a7.x;
        float s1 = a0.y + a1.y + a2.y + a3.y + a4.y + a5.y + a6.y + a7.y;
        a0 = __half22float2(frow[k2.x]);
        a1 = __half22float2(frow[k2.y]);
        a2 = __half22float2(frow[k2.z]);
        a3 = __half22float2(frow[k2.w]);
        a4 = __half22float2(frow[k3.x]);
        a5 = __half22float2(frow[k3.y]);
        a6 = __half22float2(frow[k3.z]);
        a7 = __half22float2(frow[k3.w]);
        s0 += a0.x + a1.x + a2.x + a3.x + a4.x + a5.x + a6.x + a7.x;
        s1 += a0.y + a1.y + a2.y + a3.y + a4.y + a5.y + a6.y + a7.y;

        float2 self = __half22float2(frow[n]);
        float* o = outc + (size_t)n * OUTC;
        o[0]  = s0 * (1.0f / (float)KK) - self.x;
        o[16] = s1 * (1.0f / (float)KK) - self.y;
    }
}

// ---------------------------------------------------------------------------
extern "C" void kernel_launch(void* const* d_in, const int* in_sizes, int n_in,
                              void* d_out, int out_size)
{
    const float* xyz      = (const float*)d_in[0];
    const float* features = (const float*)d_in[1];
    float* out = (float*)d_out;

    knn_kernel<<<dim3(NN / QW, BB), 256>>>(xyz, out);

    cudaFuncSetAttribute(gather_kernel,
                         cudaFuncAttributeMaxDynamicSharedMemorySize, SMEMB);
    gather_kernel<<<dim3(CC / CTP, BB), 1024, SMEMB>>>(features, out);
}